// round 16
// baseline (speedup 1.0000x reference)
#include <cuda_runtime.h>
#include <cstdint>

// GraphPool: out[s,a,f] = (deg(s,a)>0) * max over {a} ∪ {e in edges[s,a,:], e>=0} of atoms[s,e,f]
// S=512, A=128, F=128, D=6.  Edges arrive as int32.
//
// R15 analysis: inner loop is NOT the binder; wave-1 TMA prologue burst
// (~2.6us, SMs idle) + 68-CTA tail (~3.5us) are. This version:
//   - cluster (2,1,1), one cluster per s, grid=1024
//   - each CTA TMA-multicasts a 32KB half-tile to both cluster CTAs
//     (halves prologue LTS traffic; both CTAs end with the full 64KB tile)
//   - each CTA computes 64 of the 128 output rows (half-size CTAs -> small tail)
// Inner loop: branchless clamp-to-self, 7 batched LDS.128, fmax tree.

#define S_DIM 512
#define A_DIM 128
#define F_DIM 128
#define D_DIM 6
#define F4        (F_DIM / 4)              // 32 float4 per row
#define TILE_F4   (A_DIM * F4)             // 4096 float4 = 64KB
#define TILE_BYTES (TILE_F4 * 16)          // 65536
#define HALF_A    (A_DIM / 2)              // 64 rows per CTA
#define SLICE_BYTES (TILE_BYTES / 2)       // 32768
#define NTHR 256
#define NWARP (NTHR / 32)                  // 8 warps, 8 rows each

// smem: [0:8) mbar | [128 : 128+64*32) padded edges (my 64 rows) | tile @2304
#define SM_EDGE_OFF 128
#define SM_TILE_OFF 2304                    // 128B aligned
#define SMEM_BYTES  (SM_TILE_OFF + TILE_BYTES)   // 67840 (x3 = 203.5KB < 228KB)

__device__ __forceinline__ uint32_t smem_u32(const void* p) {
    uint32_t a;
    asm("{ .reg .u64 t; cvta.to.shared.u64 t, %1; cvt.u32.u64 %0, t; }" : "=r"(a) : "l"(p));
    return a;
}

__device__ __forceinline__ float4 fmax4(float4 a, float4 b) {
    return make_float4(fmaxf(a.x, b.x), fmaxf(a.y, b.y),
                       fmaxf(a.z, b.z), fmaxf(a.w, b.w));
}

__global__ __launch_bounds__(NTHR, 3) __cluster_dims__(2, 1, 1)
void graphpool_kernel(const float* __restrict__ atoms,
                      const int* __restrict__ edges,
                      float* __restrict__ out) {
    extern __shared__ __align__(128) char smem[];
    const uint32_t smem_base = smem_u32(smem);
    char* epad = smem + SM_EDGE_OFF;                     // 32B rows, 64 rows
    const float4* tile = reinterpret_cast<const float4*>(smem + SM_TILE_OFF);

    const int tid  = threadIdx.x;
    const int s    = blockIdx.x >> 1;
    uint32_t rank;
    asm("mov.u32 %0, %%cluster_ctarank;" : "=r"(rank));  // 0 or 1

    const uint32_t mbar    = smem_base;
    const uint32_t tile_sm = smem_base + SM_TILE_OFF;

    if (tid == 0) {
        asm volatile("mbarrier.init.shared.b64 [%0], 1;" :: "r"(mbar) : "memory");
    }
    __syncthreads();

    // Cluster sync: both CTAs' mbarriers must be live before any multicast
    // delivery can target them.
    asm volatile("barrier.cluster.arrive.aligned;" ::: "memory");
    asm volatile("barrier.cluster.wait.aligned;"   ::: "memory");

    if (tid == 0) {
        // Expect the FULL tile (my slice + peer's multicast slice).
        asm volatile("mbarrier.arrive.expect_tx.shared.b64 _, [%0], %1;"
                     :: "r"(mbar), "r"((uint32_t)TILE_BYTES) : "memory");
        // Load my 32KB half-slice (rows [rank*64, rank*64+64)) and multicast
        // it to both cluster CTAs at the same smem offset.
        const float* src = atoms + (size_t)s * (A_DIM * F_DIM)
                                 + (size_t)rank * HALF_A * F_DIM;
        const uint32_t dst = tile_sm + rank * SLICE_BYTES;
        asm volatile(
            "cp.async.bulk.shared::cluster.global.mbarrier::complete_tx::bytes"
            ".multicast::cluster [%0], [%1], %2, [%3], %4;"
            :: "r"(dst), "l"(src), "r"((uint32_t)SLICE_BYTES), "r"(mbar),
               "h"((uint16_t)0x3)
            : "memory");
    }

    // Stage MY 64 rows' edges into 32B-padded smem rows while TMA flies.
    if (tid < HALF_A) {
        const int* gr = edges + (size_t)s * (A_DIM * D_DIM)
                              + (size_t)(rank * HALF_A + tid) * D_DIM;
        const int2 x0 = *reinterpret_cast<const int2*>(gr);
        const int2 x1 = *reinterpret_cast<const int2*>(gr + 2);
        const int2 x2 = *reinterpret_cast<const int2*>(gr + 4);
        char* er = epad + tid * 32;
        *reinterpret_cast<int4*>(er)      = make_int4(x0.x, x0.y, x1.x, x1.y);
        *reinterpret_cast<int2*>(er + 16) = x2;
    }
    __syncthreads();

    // Wait for the full tile (phase 0): flips after 64KB delivered here.
    {
        uint32_t done;
        asm volatile(
            "{\n\t.reg .pred p;\n\t"
            "mbarrier.try_wait.parity.acquire.cta.shared::cta.b64 p, [%1], 0;\n\t"
            "selp.b32 %0, 1, 0, p;\n\t}"
            : "=r"(done) : "r"(mbar) : "memory");
        if (!done) {
            asm volatile(
                "{\n\t.reg .pred P1;\n\t"
                "WL_%=:\n\t"
                "mbarrier.try_wait.parity.acquire.cta.shared::cta.b64 P1, [%0], 0, 0x989680;\n\t"
                "@P1 bra.uni WD_%=;\n\t"
                "bra.uni WL_%=;\n\t"
                "WD_%=:\n\t}"
                :: "r"(mbar) : "memory");
        }
    }

    const int lane = tid & 31;
    const int warp = tid >> 5;
    const int abase = rank * HALF_A;

    float4* gout = reinterpret_cast<float4*>(out) + (size_t)s * TILE_F4;

#pragma unroll 2
    for (int al = warp; al < HALF_A; al += NWARP) {
        const char* er = epad + al * 32;
        const int4 E0 = *reinterpret_cast<const int4*>(er);
        const int2 E1 = *reinterpret_cast<const int2*>(er + 16);
        const int a = abase + al;                   // global row id

        // deg==0  <=>  all edges -1  <=>  max(e) < 0
        const int emax = max(max(max(E0.x, E0.y), max(E0.z, E0.w)),
                             max(E1.x, E1.y));
        const float m = (emax >= 0) ? 1.0f : 0.0f;

        // Branchless: clamp missing edges to self row (fmax no-op).
        const int i0 = (E0.x < 0) ? a : E0.x;
        const int i1 = (E0.y < 0) ? a : E0.y;
        const int i2 = (E0.z < 0) ? a : E0.z;
        const int i3 = (E0.w < 0) ? a : E0.w;
        const int i4 = (E1.x < 0) ? a : E1.x;
        const int i5 = (E1.y < 0) ? a : E1.y;

        // 7 independent gathers over the full tile, 3-deep fmax tree.
        const float4 gs = tile[a  * F4 + lane];
        const float4 g0 = tile[i0 * F4 + lane];
        const float4 g1 = tile[i1 * F4 + lane];
        const float4 g2 = tile[i2 * F4 + lane];
        const float4 g3 = tile[i3 * F4 + lane];
        const float4 g4 = tile[i4 * F4 + lane];
        const float4 g5 = tile[i5 * F4 + lane];

        float4 v = fmax4(fmax4(fmax4(gs, g0), fmax4(g1, g2)),
                         fmax4(fmax4(g3, g4), g5));

        v.x *= m; v.y *= m; v.z *= m; v.w *= m;

        gout[a * F4 + lane] = v;                    // coalesced 512B per warp
    }

    // Cluster exit sync: keep smem alive until the peer is done with
    // multicast deliveries / tile reads tied to this cluster.
    asm volatile("barrier.cluster.arrive.aligned;" ::: "memory");
    asm volatile("barrier.cluster.wait.aligned;"   ::: "memory");
}

extern "C" void kernel_launch(void* const* d_in, const int* in_sizes, int n_in,
                              void* d_out, int out_size) {
    const float* atoms = (const float*)d_in[0];
    const int*   edges = (const int*)d_in[1];
    float*       out   = (float*)d_out;

    cudaFuncSetAttribute(graphpool_kernel,
                         cudaFuncAttributeMaxDynamicSharedMemorySize, SMEM_BYTES);

    graphpool_kernel<<<S_DIM * 2, NTHR, SMEM_BYTES>>>(atoms, edges, out);
}

// round 17
// speedup vs baseline: 1.0935x; 1.0935x over previous
#include <cuda_runtime.h>
#include <cstdint>

// GraphPool: out[s,a,f] = (deg(s,a)>0) * max over {a} ∪ {e in edges[s,a,:], e>=0} of atoms[s,e,f]
// S=512, A=128, F=128, D=6.  Edges arrive as int32.
//
// PERSISTENT + DOUBLE-BUFFERED: grid = #SMs (1 CTA/SM, ~136KB smem), each CTA
// processes s = bid, bid+grid, ... with two 64KB tile buffers. TMA for tile
// i+2 is issued right after tile i's compute finishes, so all tile loads after
// the first are hidden behind compute; the ragged 68-CTA second wave of the
// old grid=512 scheme becomes a ±1-tile imbalance.
// Inner loop: branchless clamp-to-self, 7 batched LDS.128, fmax tree (R14 body).

#define S_DIM 512
#define A_DIM 128
#define F_DIM 128
#define D_DIM 6
#define F4        (F_DIM / 4)            // 32 float4 per row
#define TILE_F4   (A_DIM * F4)           // 4096 float4 = 64KB
#define TILE_BYTES (TILE_F4 * 16)
#define NTHR  1024
#define NWARP (NTHR / 32)                // 32 warps, 4 rows each

// smem: mbar[2] @0 | ebuf0 @128 (128x32B) | ebuf1 @4224 | tile0 @8320 | tile1 @73856
#define SM_E0 128
#define SM_E1 (SM_E0 + A_DIM * 32)           // 4224
#define SM_T0 (SM_E1 + A_DIM * 32)           // 8320  (128B aligned)
#define SM_T1 (SM_T0 + TILE_BYTES)           // 73856 (128B aligned)
#define SMEM_BYTES (SM_T1 + TILE_BYTES)      // 139392

__device__ __forceinline__ uint32_t smem_u32(const void* p) {
    uint32_t a;
    asm("{ .reg .u64 t; cvta.to.shared.u64 t, %1; cvt.u32.u64 %0, t; }" : "=r"(a) : "l"(p));
    return a;
}

__device__ __forceinline__ float4 fmax4(float4 a, float4 b) {
    return make_float4(fmaxf(a.x, b.x), fmaxf(a.y, b.y),
                       fmaxf(a.z, b.z), fmaxf(a.w, b.w));
}

// Stage one tile's edges into 32B-padded smem rows (tid<128 active).
__device__ __forceinline__ void stage_edges(const int* __restrict__ edges,
                                            int s, char* ebuf, int tid) {
    if (tid < A_DIM) {
        const int* gr = edges + (size_t)s * (A_DIM * D_DIM) + tid * D_DIM;
        const int2 x0 = *reinterpret_cast<const int2*>(gr);
        const int2 x1 = *reinterpret_cast<const int2*>(gr + 2);
        const int2 x2 = *reinterpret_cast<const int2*>(gr + 4);
        char* er = ebuf + tid * 32;
        *reinterpret_cast<int4*>(er)      = make_int4(x0.x, x0.y, x1.x, x1.y);
        *reinterpret_cast<int2*>(er + 16) = x2;
    }
}

__device__ __forceinline__ void tma_issue(uint32_t dst, const float* src,
                                          uint32_t mbar) {
    asm volatile("mbarrier.arrive.expect_tx.shared.b64 _, [%0], %1;"
                 :: "r"(mbar), "r"((uint32_t)TILE_BYTES) : "memory");
    asm volatile(
        "cp.async.bulk.shared::cta.global.mbarrier::complete_tx::bytes "
        "[%0], [%1], %2, [%3];"
        :: "r"(dst), "l"(src), "r"((uint32_t)TILE_BYTES), "r"(mbar)
        : "memory");
}

__device__ __forceinline__ void mbar_wait(uint32_t mbar, uint32_t parity) {
    uint32_t done;
    asm volatile(
        "{\n\t.reg .pred p;\n\t"
        "mbarrier.try_wait.parity.acquire.cta.shared::cta.b64 p, [%1], %2;\n\t"
        "selp.b32 %0, 1, 0, p;\n\t}"
        : "=r"(done) : "r"(mbar), "r"(parity) : "memory");
    if (!done) {
        asm volatile(
            "{\n\t.reg .pred P1;\n\t"
            "WL_%=:\n\t"
            "mbarrier.try_wait.parity.acquire.cta.shared::cta.b64 P1, [%0], %1, 0x989680;\n\t"
            "@P1 bra.uni WD_%=;\n\t"
            "bra.uni WL_%=;\n\t"
            "WD_%=:\n\t}"
            :: "r"(mbar), "r"(parity) : "memory");
    }
}

__global__ __launch_bounds__(NTHR, 1)
void graphpool_kernel(const float* __restrict__ atoms,
                      const int* __restrict__ edges,
                      float* __restrict__ out) {
    extern __shared__ __align__(128) char smem[];
    const uint32_t smem_base = smem_u32(smem);
    const int tid  = threadIdx.x;
    const int bid  = blockIdx.x;
    const int grid = gridDim.x;
    const int ntiles = (S_DIM - bid + grid - 1) / grid;   // 3 or 4

    if (tid == 0) {
        asm volatile("mbarrier.init.shared.b64 [%0], 1;" :: "r"(smem_base)     : "memory");
        asm volatile("mbarrier.init.shared.b64 [%0], 1;" :: "r"(smem_base + 8) : "memory");
        asm volatile("fence.proxy.async.shared::cta;" ::: "memory");
    }
    __syncthreads();

    // Prologue: kick off tiles 0 and 1, stage their edges.
    if (tid == 0) {
        tma_issue(smem_base + SM_T0,
                  atoms + (size_t)bid * (A_DIM * F_DIM), smem_base);
        if (ntiles > 1)
            tma_issue(smem_base + SM_T1,
                      atoms + (size_t)(bid + grid) * (A_DIM * F_DIM), smem_base + 8);
    }
    stage_edges(edges, bid, smem + SM_E0, tid);
    if (ntiles > 1) stage_edges(edges, bid + grid, smem + SM_E1, tid);
    __syncthreads();

    const int lane = tid & 31;
    const int warp = tid >> 5;

    for (int i = 0; i < ntiles; i++) {
        const int b = i & 1;
        const uint32_t mbar = smem_base + b * 8;
        const uint32_t parity = (i >> 1) & 1;      // stateless phase tracking
        mbar_wait(mbar, parity);

        const int s = bid + i * grid;
        const char* ebuf = smem + (b ? SM_E1 : SM_E0);
        const float4* tile = reinterpret_cast<const float4*>(smem + (b ? SM_T1 : SM_T0));
        float4* gout = reinterpret_cast<float4*>(out) + (size_t)s * TILE_F4;

#pragma unroll 2
        for (int a = warp; a < A_DIM; a += NWARP) {
            const char* er = ebuf + a * 32;
            const int4 E0 = *reinterpret_cast<const int4*>(er);
            const int2 E1 = *reinterpret_cast<const int2*>(er + 16);

            // deg==0  <=>  all edges -1  <=>  max(e) < 0
            const int emax = max(max(max(E0.x, E0.y), max(E0.z, E0.w)),
                                 max(E1.x, E1.y));
            const float m = (emax >= 0) ? 1.0f : 0.0f;

            // Branchless: clamp missing edges to self row (fmax no-op).
            const int i0 = (E0.x < 0) ? a : E0.x;
            const int i1 = (E0.y < 0) ? a : E0.y;
            const int i2 = (E0.z < 0) ? a : E0.z;
            const int i3 = (E0.w < 0) ? a : E0.w;
            const int i4 = (E1.x < 0) ? a : E1.x;
            const int i5 = (E1.y < 0) ? a : E1.y;

            // 7 independent gathers, 3-deep fmax tree.
            const float4 gs = tile[a  * F4 + lane];
            const float4 g0 = tile[i0 * F4 + lane];
            const float4 g1 = tile[i1 * F4 + lane];
            const float4 g2 = tile[i2 * F4 + lane];
            const float4 g3 = tile[i3 * F4 + lane];
            const float4 g4 = tile[i4 * F4 + lane];
            const float4 g5 = tile[i5 * F4 + lane];

            float4 v = fmax4(fmax4(fmax4(gs, g0), fmax4(g1, g2)),
                             fmax4(fmax4(g3, g4), g5));

            v.x *= m; v.y *= m; v.z *= m; v.w *= m;

            gout[a * F4 + lane] = v;               // coalesced 512B per warp
        }

        __syncthreads();   // all warps done reading buffer b

        const int inext = i + 2;
        if (inext < ntiles) {
            const int snext = bid + inext * grid;
            if (tid == 0) {
                tma_issue(smem_base + (b ? SM_T1 : SM_T0),
                          atoms + (size_t)snext * (A_DIM * F_DIM), mbar);
            }
            stage_edges(edges, snext, smem + (b ? SM_E1 : SM_E0), tid);
            // Visibility of these STS to readers is covered by the
            // __syncthreads at the end of iteration i+1.
        }
    }
}

extern "C" void kernel_launch(void* const* d_in, const int* in_sizes, int n_in,
                              void* d_out, int out_size) {
    const float* atoms = (const float*)d_in[0];
    const int*   edges = (const int*)d_in[1];
    float*       out   = (float*)d_out;

    cudaFuncSetAttribute(graphpool_kernel,
                         cudaFuncAttributeMaxDynamicSharedMemorySize, SMEM_BYTES);

    int sms = 148;
    cudaDeviceGetAttribute(&sms, cudaDevAttrMultiProcessorCount, 0);  // query only, capture-safe
    if (sms < 1 || sms > S_DIM) sms = 148;

    graphpool_kernel<<<sms, NTHR, SMEM_BYTES>>>(atoms, edges, out);
}